// round 14
// baseline (speedup 1.0000x reference)
#include <cuda_runtime.h>
#include <cuda_bf16.h>
#include <cstdint>

#define IC    256
#define OC    128
#define HIN   32
#define WIN_  32
#define NB    32
#define ICPC  8
#define NCHUNK 32
#define ROWB  80          // bytes per k-row: 32 bf16 = 64B + 16B pad (conflict-free ldmatrix)

// ---- dynamic SMEM layout (bytes) ----
// A:   3 bufs x [hl][128][ROWB] = 3*20480 = 61440
// B:   2 bufs x [hl][128][ROWB] = 2*20480 = 40960
// WIN: 2 bufs x (8 ic x 5 rows x 36 floats) = 2*5760 = 11520
#define SM_A    0
#define SM_B    61440
#define SM_WIN  102400
#define WIN_ROWF 36
#define WINBUF  5760
#define SMEM_TOTAL 113920    // x2 CTAs = 227840 < 228KB/SM

// Pre-laid-out A: [p][chunk][128 oc][ROWB]
__device__ __align__(16) unsigned char g_Ah[4 * 32 * 128 * ROWB];
__device__ __align__(16) unsigned char g_Al[4 * 32 * 128 * ROWB];

// ---------------- asm helpers ----------------
__device__ __forceinline__ uint32_t smem_u32(const void* p) {
    uint32_t a;
    asm("{ .reg .u64 t; cvta.to.shared.u64 t, %1; cvt.u32.u64 %0, t; }" : "=r"(a) : "l"(p));
    return a;
}
__device__ __forceinline__ void cp16(uint32_t d, const void* s) {
    asm volatile("cp.async.cg.shared.global [%0], [%1], 16;" :: "r"(d), "l"(s) : "memory");
}
__device__ __forceinline__ void cp8z(uint32_t d, const void* s, int sz) {
    asm volatile("cp.async.ca.shared.global [%0], [%1], 8, %2;" :: "r"(d), "l"(s), "r"(sz) : "memory");
}
__device__ __forceinline__ void cp_commit() { asm volatile("cp.async.commit_group;" ::: "memory"); }
template <int N> __device__ __forceinline__ void cp_wait() {
    asm volatile("cp.async.wait_group %0;" :: "n"(N) : "memory");
}
__device__ __forceinline__ uint32_t bf16x2_of(float lo, float hi) {
    uint32_t r;
    asm("cvt.rn.bf16x2.f32 %0, %1, %2;" : "=r"(r) : "f"(hi), "f"(lo));
    return r;
}
#define LDSM4(r, a)                                                              \
    asm volatile("ldmatrix.sync.aligned.m8n8.x4.shared.b16 {%0,%1,%2,%3}, [%4];" \
                 : "=r"((r)[0]), "=r"((r)[1]), "=r"((r)[2]), "=r"((r)[3])        \
                 : "r"(a))
#define MMA(c, a, b0, b1)                                                        \
    asm volatile("mma.sync.aligned.m16n8k16.row.col.f32.bf16.bf16.f32 "          \
                 "{%0,%1,%2,%3},{%4,%5,%6,%7},{%8,%9},{%0,%1,%2,%3};"            \
                 : "+f"((c)[0]), "+f"((c)[1]), "+f"((c)[2]), "+f"((c)[3])        \
                 : "r"((a)[0]), "r"((a)[1]), "r"((a)[2]), "r"((a)[3]),           \
                   "r"(b0), "r"(b1))

// ---------------- weight transform ----------------
__global__ void wt_kernel(const float* __restrict__ W) {
    int idx = blockIdx.x * blockDim.x + threadIdx.x;   // 2^19
    int k  = idx & 31;
    int oc = (idx >> 5) & 127;
    int ck = (idx >> 12) & 31;
    int p  = idx >> 17;
    int tap = k & 3, icl = k >> 2;
    int ic = ck * ICPC + icl;
    int kh = 2 * (tap >> 1) + (p >> 1);
    int kw = 2 * (tap & 1) + (p & 1);
    float v = W[((oc * IC + ic) * 4 + kh) * 4 + kw];
    __nv_bfloat16 h = __float2bfloat16(v);
    __nv_bfloat16 l = __float2bfloat16(v - __bfloat162float(h));
    size_t off = ((size_t)(p * 32 + ck) * 128 + oc) * ROWB + k * 2;
    *(__nv_bfloat16*)(g_Ah + off) = h;
    *(__nv_bfloat16*)(g_Al + off) = l;
}

// ---------------- main kernel ----------------
// grid (8 a-blocks, 32 batches, 4 parities) = 1024 CTAs, 2 CTAs/SM.
// CTA tile: D[128 oc][128 n], n = a_l*32 + c_l (a_l 0..3), ta = blockIdx.x*4.
__global__ __launch_bounds__(256, 2)
void tconv_hmma(const float* __restrict__ x,
                const float* __restrict__ bias,
                float* __restrict__ y) {
    extern __shared__ char smem[];
    const uint32_t sb = smem_u32(smem);
    const int tid = threadIdx.x;
    const int warp = tid >> 5, lane = tid & 31;
    const int wm = warp & 1, wn = warp >> 1;
    const int p = blockIdx.z, b = blockIdx.y;
    const int rh = p >> 1, rw = p & 1;
    const int ta = blockIdx.x * 4;

    const int g = lane >> 3, r = lane & 7;
    const uint32_t a_lane = (uint32_t)(((g & 1) * 8 + r) * ROWB + (g >> 1) * 16);
    const uint32_t b_lane = (uint32_t)(((g >> 1) * 8 + r) * ROWB + (g & 1) * 16);

    // expand-role constants
    const int en = tid & 127, ehalf = tid >> 7;
    const int e_a = en >> 5, e_c = en & 31;
    const int e_q0 = e_c + rw + 1;

    float C[4][4][4];
    #pragma unroll
    for (int i = 0; i < 4; i++)
        #pragma unroll
        for (int j = 0; j < 4; j++)
            #pragma unroll
            for (int q = 0; q < 4; q++) C[i][j][q] = 0.f;

    auto loadA = [&](int chunk, int abuf) {
        const unsigned char* sh = g_Ah + (size_t)(p * 32 + chunk) * (128 * ROWB);
        const unsigned char* sl = g_Al + (size_t)(p * 32 + chunk) * (128 * ROWB);
        uint32_t dh = sb + SM_A + abuf * 20480;
        uint32_t dl = dh + 10240;
        #pragma unroll
        for (int t = 0; t < 3; t++) {
            int i = tid + t * 256;
            if (i < 640) {
                cp16(dh + i * 16, sh + i * 16);
                cp16(dl + i * 16, sl + i * 16);
            }
        }
    };
    // WIN(chunk) -> buffer chunk&1
    auto loadWin = [&](int chunk) {
        uint32_t wb = sb + SM_WIN + (chunk & 1) * WINBUF;
        #pragma unroll
        for (int t = 0; t < 3; t++) {
            int i = tid + t * 256;
            if (i < ICPC * 5 * 18) {
                int icl = i / 90;
                int rem = i - icl * 90;
                int rr = rem / 18;
                int piece = rem - rr * 18;
                int ih = ta + rh - 1 + rr;
                bool rv = (unsigned)ih < HIN;
                int ihc = rv ? ih : 0;
                bool mid = (piece >= 1) && (piece <= 16);
                int iw0 = mid ? (piece - 1) * 2 : 0;
                const char* src = (const char*)x +
                    ((((size_t)b * IC + chunk * ICPC + icl) * HIN + ihc) * WIN_ + iw0) * 4;
                uint32_t dst = wb + (icl * 5 + rr) * (WIN_ROWF * 4) + piece * 8;
                cp8z(dst, src, (rv && mid) ? 8 : 0);
            }
        }
    };
    // expand 2 icl's of B rows into B[bbuf] from WIN[wbuf]
    auto expand_part = [&](int bbuf, int wbuf, int part) {
        const float* winf = (const float*)(smem + SM_WIN - 0) + (SM_WIN, 0);
        (void)winf;
        const float* wf = (const float*)(smem + SM_WIN + wbuf * WINBUF);
        char* bh = smem + SM_B + bbuf * 20480 + en * ROWB;
        char* bl = bh + 10240;
        #pragma unroll
        for (int t = 0; t < 2; t++) {
            int icl = ehalf * 4 + part * 2 + t;
            const float* w0 = wf + (icl * 5 + e_a) * WIN_ROWF + e_q0;
            float v00 = w0[0], v01 = w0[1];
            float v10 = w0[WIN_ROWF], v11 = w0[WIN_ROWF + 1];
            uint32_t h01 = bf16x2_of(v00, v01);
            uint32_t h23 = bf16x2_of(v10, v11);
            float r00 = __uint_as_float(h01 << 16);
            float r01 = __uint_as_float(h01 & 0xFFFF0000u);
            float r10 = __uint_as_float(h23 << 16);
            float r11 = __uint_as_float(h23 & 0xFFFF0000u);
            uint32_t l01 = bf16x2_of(v00 - r00, v01 - r01);
            uint32_t l23 = bf16x2_of(v10 - r10, v11 - r11);
            *(uint2*)(bh + icl * 8) = make_uint2(h01, h23);
            *(uint2*)(bl + icl * 8) = make_uint2(l01, l23);
        }
    };
    // compute chunk (A in abuf, B in cbuf); fuse expand of next chunk into ebuf from wbuf
    auto compute_fused = [&](int abuf, int cbuf, int ebuf, int wbuf, bool do_exp) {
        uint32_t Ah = sb + SM_A + abuf * 20480 + wm * (64 * ROWB) + a_lane;
        uint32_t Al = Ah + 10240;
        uint32_t Bh = sb + SM_B + cbuf * 20480 + wn * (32 * ROWB) + b_lane;
        uint32_t Bl = Bh + 10240;
        #pragma unroll
        for (int ks = 0; ks < 2; ks++) {
            uint32_t ah[4][4], al[4][4];
            #pragma unroll
            for (int tm = 0; tm < 4; tm++) {
                LDSM4(ah[tm], Ah + tm * (16 * ROWB) + ks * 32);
                LDSM4(al[tm], Al + tm * (16 * ROWB) + ks * 32);
            }
            #pragma unroll
            for (int tn = 0; tn < 2; tn++) {
                uint32_t bhf[4], blf[4];
                LDSM4(bhf, Bh + tn * (16 * ROWB) + ks * 32);
                LDSM4(blf, Bl + tn * (16 * ROWB) + ks * 32);
                #pragma unroll
                for (int tm = 0; tm < 4; tm++) {
                    #pragma unroll
                    for (int h = 0; h < 2; h++) {
                        float* c = C[tm][tn * 2 + h];
                        MMA(c, ah[tm], bhf[2 * h], bhf[2 * h + 1]);
                        MMA(c, ah[tm], blf[2 * h], blf[2 * h + 1]);
                        MMA(c, al[tm], bhf[2 * h], bhf[2 * h + 1]);
                    }
                }
            }
            if (do_exp) expand_part(ebuf, wbuf, ks);   // A frags dead here
        }
    };

    // ---- prologue: establish pending = {g1, g2}, B0 expanded ----
    loadWin(0); loadA(0, 0); cp_commit();   // g0
    loadWin(1); loadA(1, 1); cp_commit();   // g1
    cp_wait<1>(); __syncthreads();          // g0 done
    expand_part(0, 0, 0); expand_part(0, 0, 1);
    __syncthreads();
    loadWin(2); loadA(2, 2); cp_commit();   // g2

    // ---- mainloop ----
    // iter i: wait g(i+1) (g(i+2) stays in flight), compute i + expand B(i+1),
    //         then issue g(i+3).
    for (int i = 0; i < NCHUNK; i++) {
        const bool have_next = (i + 1 < NCHUNK);
        if (have_next) {
            if (i + 3 < NCHUNK) cp_wait<1>(); else cp_wait<0>();
            __syncthreads();
        }
        compute_fused(i % 3, i & 1, (i + 1) & 1, (i + 1) & 1, have_next);
        if (have_next) {
            __syncthreads();
            if (i + 3 < NCHUNK) { loadWin(i + 3); loadA(i + 3, (i + 3) % 3); cp_commit(); }
        }
    }

    // ---- epilogue: scatter C + bias ----
    {
        const int row = lane >> 2, qc = lane & 3;
        const int oh = 2 * (ta + wn) + rh;
        #pragma unroll
        for (int tm = 0; tm < 4; tm++) {
            const int oc0 = wm * 64 + tm * 16 + row;
            const float bv0 = bias[oc0];
            const float bv1 = bias[oc0 + 8];
            #pragma unroll
            for (int f = 0; f < 4; f++) {
                const int c_l = f * 8 + 2 * qc;
                const int ow = 2 * c_l + rw;
                float* yp = y + (((size_t)b * OC + oc0) * 64 + oh) * 64 + ow;
                yp[0] = C[tm][f][0] + bv0;
                yp[2] = C[tm][f][1] + bv0;
                float* yp8 = yp + 8 * 64 * 64;
                yp8[0] = C[tm][f][2] + bv1;
                yp8[2] = C[tm][f][3] + bv1;
            }
        }
    }
}

extern "C" void kernel_launch(void* const* d_in, const int* in_sizes, int n_in,
                              void* d_out, int out_size) {
    const float* x    = (const float*)d_in[0];
    const float* W    = (const float*)d_in[1];
    const float* bias = (const float*)d_in[2];
    float* y = (float*)d_out;

    cudaFuncSetAttribute(tconv_hmma, cudaFuncAttributeMaxDynamicSharedMemorySize, SMEM_TOTAL);

    wt_kernel<<<2048, 256>>>(W);

    dim3 grid(8, NB, 4);
    tconv_hmma<<<grid, 256, SMEM_TOTAL>>>(x, bias, y);
}

// round 17
// speedup vs baseline: 1.3868x; 1.3868x over previous
#include <cuda_runtime.h>
#include <cuda_fp16.h>
#include <cstdint>

#define IC    256
#define OC    128
#define HIN   32
#define WIN_  32
#define NB    32
#define ICPC  8
#define NCHUNK 32
#define ROWB  80          // bytes per k-row: 32 fp16 = 64B + 16B pad (conflict-free ldmatrix)

// ---- dynamic SMEM layout (bytes) ----
// A:   3 bufs x [hl][128][ROWB] = 3*20480 = 61440
// B:   2 bufs x [128][ROWB]     = 2*10240 = 20480
// WIN: 3 bufs x (8 ic x 5 rows x 36 floats) = 3*5760 = 17280
#define SM_A    0
#define SM_B    61440
#define SM_WIN  81920
#define WIN_ROWF 36
#define WINBUF  5760
#define SMEM_TOTAL 99200     // x2 CTAs = 198400 < 228KB/SM

// Pre-laid-out A: [p][chunk][128 oc][ROWB]  (fp16 hi / lo)
__device__ __align__(16) unsigned char g_Ah[4 * 32 * 128 * ROWB];
__device__ __align__(16) unsigned char g_Al[4 * 32 * 128 * ROWB];

// ---------------- asm helpers ----------------
__device__ __forceinline__ uint32_t smem_u32(const void* p) {
    uint32_t a;
    asm("{ .reg .u64 t; cvta.to.shared.u64 t, %1; cvt.u32.u64 %0, t; }" : "=r"(a) : "l"(p));
    return a;
}
__device__ __forceinline__ void cp16(uint32_t d, const void* s) {
    asm volatile("cp.async.cg.shared.global [%0], [%1], 16;" :: "r"(d), "l"(s) : "memory");
}
__device__ __forceinline__ void cp8z(uint32_t d, const void* s, int sz) {
    asm volatile("cp.async.ca.shared.global [%0], [%1], 8, %2;" :: "r"(d), "l"(s), "r"(sz) : "memory");
}
__device__ __forceinline__ void cp_commit() { asm volatile("cp.async.commit_group;" ::: "memory"); }
template <int N> __device__ __forceinline__ void cp_wait() {
    asm volatile("cp.async.wait_group %0;" :: "n"(N) : "memory");
}
// pack two floats into f16x2: low half = lo, high half = hi
__device__ __forceinline__ uint32_t f16x2_of(float lo, float hi) {
    uint32_t r;
    asm("cvt.rn.f16x2.f32 %0, %1, %2;" : "=r"(r) : "f"(hi), "f"(lo));
    return r;
}
#define LDSM4(r, a)                                                              \
    asm volatile("ldmatrix.sync.aligned.m8n8.x4.shared.b16 {%0,%1,%2,%3}, [%4];" \
                 : "=r"((r)[0]), "=r"((r)[1]), "=r"((r)[2]), "=r"((r)[3])        \
                 : "r"(a))
#define MMA(c, a, b0, b1)                                                        \
    asm volatile("mma.sync.aligned.m16n8k16.row.col.f32.f16.f16.f32 "            \
                 "{%0,%1,%2,%3},{%4,%5,%6,%7},{%8,%9},{%0,%1,%2,%3};"            \
                 : "+f"((c)[0]), "+f"((c)[1]), "+f"((c)[2]), "+f"((c)[3])        \
                 : "r"((a)[0]), "r"((a)[1]), "r"((a)[2]), "r"((a)[3]),           \
                   "r"(b0), "r"(b1))

// ---------------- weight transform ----------------
// A[oc][k] = W[oc][ck*8+icl][2j+rh][2i+rw], k = icl*4 + (j*2+i). fp16 hi/lo split.
__global__ void wt_kernel(const float* __restrict__ W) {
    int idx = blockIdx.x * blockDim.x + threadIdx.x;   // 2^19
    int k  = idx & 31;
    int oc = (idx >> 5) & 127;
    int ck = (idx >> 12) & 31;
    int p  = idx >> 17;
    int tap = k & 3, icl = k >> 2;
    int ic = ck * ICPC + icl;
    int kh = 2 * (tap >> 1) + (p >> 1);
    int kw = 2 * (tap & 1) + (p & 1);
    float v = W[((oc * IC + ic) * 4 + kh) * 4 + kw];
    __half h = __float2half_rn(v);
    __half l = __float2half_rn(v - __half2float(h));
    size_t off = ((size_t)(p * 32 + ck) * 128 + oc) * ROWB + k * 2;
    *(__half*)(g_Ah + off) = h;
    *(__half*)(g_Al + off) = l;
}

// ---------------- main kernel ----------------
// grid (8 a-blocks, 32 batches, 4 parities) = 1024 CTAs, 2 CTAs/SM.
// CTA tile: D[128 oc][128 n], n = a_l*32 + c_l (a_l 0..3), ta = blockIdx.x*4.
// 2-term fp16 emulation: y = AH*B + AL*B  (A to 22 bits; error = B fp16 rounding).
__global__ __launch_bounds__(256, 2)
void tconv_hmma(const float* __restrict__ x,
                const float* __restrict__ bias,
                float* __restrict__ y) {
    extern __shared__ char smem[];
    const uint32_t sb = smem_u32(smem);
    const int tid = threadIdx.x;
    const int warp = tid >> 5, lane = tid & 31;
    const int wm = warp & 1, wn = warp >> 1;
    const int p = blockIdx.z, b = blockIdx.y;
    const int rh = p >> 1, rw = p & 1;
    const int ta = blockIdx.x * 4;

    const int g = lane >> 3, r = lane & 7;
    const uint32_t a_lane = (uint32_t)(((g & 1) * 8 + r) * ROWB + (g >> 1) * 16);
    const uint32_t b_lane = (uint32_t)(((g >> 1) * 8 + r) * ROWB + (g & 1) * 16);

    // expand-role constants
    const int en = tid & 127, ehalf = tid >> 7;
    const int e_a = en >> 5, e_c = en & 31;
    const int e_q0 = e_c + rw + 1;

    float C[4][4][4];
    #pragma unroll
    for (int i = 0; i < 4; i++)
        #pragma unroll
        for (int j = 0; j < 4; j++)
            #pragma unroll
            for (int q = 0; q < 4; q++) C[i][j][q] = 0.f;

    auto loadA = [&](int chunk, int abuf) {
        const unsigned char* sh = g_Ah + (size_t)(p * 32 + chunk) * (128 * ROWB);
        const unsigned char* sl = g_Al + (size_t)(p * 32 + chunk) * (128 * ROWB);
        uint32_t dh = sb + SM_A + abuf * 20480;
        uint32_t dl = dh + 10240;
        #pragma unroll
        for (int t = 0; t < 3; t++) {
            int i = tid + t * 256;
            if (i < 640) {
                cp16(dh + i * 16, sh + i * 16);
                cp16(dl + i * 16, sl + i * 16);
            }
        }
    };
    // WIN(chunk) -> buffer chunk%3; rows rr=0..4: ih = ta+rh-1+rr; col s: iw = s-2
    auto loadWin = [&](int chunk) {
        uint32_t wb = sb + SM_WIN + (chunk % 3) * WINBUF;
        #pragma unroll
        for (int t = 0; t < 3; t++) {
            int i = tid + t * 256;
            if (i < ICPC * 5 * 18) {
                int icl = i / 90;
                int rem = i - icl * 90;
                int rr = rem / 18;
                int piece = rem - rr * 18;
                int ih = ta + rh - 1 + rr;
                bool rv = (unsigned)ih < HIN;
                int ihc = rv ? ih : 0;
                bool mid = (piece >= 1) && (piece <= 16);
                int iw0 = mid ? (piece - 1) * 2 : 0;
                const char* src = (const char*)x +
                    ((((size_t)b * IC + chunk * ICPC + icl) * HIN + ihc) * WIN_ + iw0) * 4;
                uint32_t dst = wb + (icl * 5 + rr) * (WIN_ROWF * 4) + piece * 8;
                cp8z(dst, src, (rv && mid) ? 8 : 0);
            }
        }
    };
    // expand chunk: WIN(chunk%3) -> B(chunk&1), single fp16, packed STS.128
    auto expand = [&](int chunk) {
        const float* wf = (const float*)(smem + SM_WIN + (chunk % 3) * WINBUF);
        char* bp = smem + SM_B + (chunk & 1) * 10240 + en * ROWB;
        #pragma unroll
        for (int t2 = 0; t2 < 2; t2++) {
            uint32_t v[4];
            #pragma unroll
            for (int u = 0; u < 2; u++) {
                int icl = ehalf * 4 + t2 * 2 + u;
                const float* w0 = wf + (icl * 5 + e_a) * WIN_ROWF + e_q0;
                v[2 * u]     = f16x2_of(w0[0], w0[1]);
                v[2 * u + 1] = f16x2_of(w0[WIN_ROWF], w0[WIN_ROWF + 1]);
            }
            *(uint4*)(bp + (ehalf * 4 + t2 * 2) * 8) = make_uint4(v[0], v[1], v[2], v[3]);
        }
    };
    auto compute = [&](int abuf, int bbuf) {
        uint32_t Ah = sb + SM_A + abuf * 20480 + wm * (64 * ROWB) + a_lane;
        uint32_t Al = Ah + 10240;
        uint32_t Bb = sb + SM_B + bbuf * 10240 + wn * (32 * ROWB) + b_lane;
        #pragma unroll
        for (int ks = 0; ks < 2; ks++) {
            uint32_t ah[4][4], al[4][4];
            #pragma unroll
            for (int tm = 0; tm < 4; tm++) {
                LDSM4(ah[tm], Ah + tm * (16 * ROWB) + ks * 32);
                LDSM4(al[tm], Al + tm * (16 * ROWB) + ks * 32);
            }
            #pragma unroll
            for (int tn = 0; tn < 2; tn++) {
                uint32_t bf[4];
                LDSM4(bf, Bb + tn * (16 * ROWB) + ks * 32);
                #pragma unroll
                for (int tm = 0; tm < 4; tm++) {
                    #pragma unroll
                    for (int h = 0; h < 2; h++) {
                        float* c = C[tm][tn * 2 + h];
                        MMA(c, ah[tm], bf[2 * h], bf[2 * h + 1]);
                        MMA(c, al[tm], bf[2 * h], bf[2 * h + 1]);
                    }
                }
            }
        }
    };

    // ---- prologue: pending = {g1, g2}, B0 expanded ----
    loadWin(0); loadA(0, 0); cp_commit();   // g0
    loadWin(1); loadA(1, 1); cp_commit();   // g1
    cp_wait<1>(); __syncthreads();          // g0 done
    expand(0);
    __syncthreads();
    loadWin(2); loadA(2, 2); cp_commit();   // g2

    // ---- mainloop ----
    // iter i: compute(i); wait g(i+1); issue g(i+3) BEFORE expand (distinct WIN/A bufs);
    //         expand(i+1); sync.
    for (int i = 0; i < NCHUNK; i++) {
        compute(i % 3, i & 1);
        if (i + 1 < NCHUNK) {
            if (i + 2 < NCHUNK) cp_wait<1>(); else cp_wait<0>();
            __syncthreads();
            if (i + 3 < NCHUNK) { loadWin(i + 3); loadA(i + 3, (i + 3) % 3); cp_commit(); }
            expand(i + 1);
            __syncthreads();
        }
    }

    // ---- epilogue: scatter C + bias ----
    {
        const int row = lane >> 2, qc = lane & 3;
        const int oh = 2 * (ta + wn) + rh;
        #pragma unroll
        for (int tm = 0; tm < 4; tm++) {
            const int oc0 = wm * 64 + tm * 16 + row;
            const float bv0 = bias[oc0];
            const float bv1 = bias[oc0 + 8];
            #pragma unroll
            for (int f = 0; f < 4; f++) {
                const int c_l = f * 8 + 2 * qc;
                const int ow = 2 * c_l + rw;
                float* yp = y + (((size_t)b * OC + oc0) * 64 + oh) * 64 + ow;
                yp[0] = C[tm][f][0] + bv0;
                yp[2] = C[tm][f][1] + bv0;
                float* yp8 = yp + 8 * 64 * 64;
                yp8[0] = C[tm][f][2] + bv1;
                yp8[2] = C[tm][f][3] + bv1;
            }
        }
    }
}

extern "C" void kernel_launch(void* const* d_in, const int* in_sizes, int n_in,
                              void* d_out, int out_size) {
    const float* x    = (const float*)d_in[0];
    const float* W    = (const float*)d_in[1];
    const float* bias = (const float*)d_in[2];
    float* y = (float*)d_out;

    cudaFuncSetAttribute(tconv_hmma, cudaFuncAttributeMaxDynamicSharedMemorySize, SMEM_TOTAL);

    wt_kernel<<<2048, 256>>>(W);

    dim3 grid(8, NB, 4);
    tconv_hmma<<<grid, 256, SMEM_TOTAL>>>(x, bias, y);
}